// round 3
// baseline (speedup 1.0000x reference)
#include <cuda_runtime.h>

// DfOp: complex order-5 causal FIR on first 96 freq bins, copy the rest.
// spec: (B=8, T=3000, F=481, 2) f32 ; coef: (B=8, T=3000, 96, 10) f32
//
// R3: flat grid-stride over two uniform work-item queues so every warp gets an
// identical workload (fixes R2's warp-specialization occupancy collapse) while
// keeping R2's 16-byte vectorized accesses (fixes R1's LSU-issue saturation).

#define T_DIM   3000
#define F_DIM   481
#define NDF     96
#define NO      5
#define NROWS   (8 * 3000)
#define DF_ITEMS (NROWS * (NDF / 2))   // one item = one (row, bin-pair)
#define CP_ITEMS (NROWS * 193)         // 192 float4 + 1 float2 per row tail

__global__ __launch_bounds__(256) void df_kernel(
    const float* __restrict__ spec,
    const float* __restrict__ coef,
    float* __restrict__ out)
{
    const float2* __restrict__ spec2 = reinterpret_cast<const float2*>(spec);
    const float4* __restrict__ spec4 = reinterpret_cast<const float4*>(spec);
    float2* __restrict__ out2 = reinterpret_cast<float2*>(out);
    float4* __restrict__ out4 = reinterpret_cast<float4*>(out);

    const int tid    = blockIdx.x * blockDim.x + threadIdx.x;
    const int stride = gridDim.x * blockDim.x;

    // ---------------- Phase 1: DF (FIR) items ----------------
    for (int it = tid; it < DF_ITEMS; it += stride) {
        const int r  = it / (NDF / 2);        // row = b*T + t
        const int j  = (it - r * (NDF / 2)) * 2;  // even bin index
        const int t  = r % T_DIM;

        // 20 coef floats for the bin pair: 16B-aligned (bytes = 3840*r + 80*(j/2))
        const float4* __restrict__ c4 =
            reinterpret_cast<const float4*>(coef + ((size_t)r * NDF + j) * (2 * NO));
        const float4 a = c4[0], b = c4[1], c = c4[2], d = c4[3], e = c4[4];
        const float cr0[NO] = {a.x, a.y, a.z, a.w, b.x};
        const float ci0[NO] = {b.y, b.z, b.w, c.x, c.y};
        const float cr1[NO] = {c.z, c.w, d.x, d.y, d.z};
        const float ci1[NO] = {d.w, e.x, e.y, e.z, e.w};

        float fr0 = 0.f, fi0 = 0.f, fr1 = 0.f, fi1 = 0.f;
        #pragma unroll
        for (int k = 0; k < NO; ++k) {
            const int tapT = t - (NO - 1) + k;
            float4 x = make_float4(0.f, 0.f, 0.f, 0.f);
            if (tapT >= 0) {
                const size_t i2 = (size_t)(r - (NO - 1) + k) * F_DIM + j;
                if ((i2 & 1) == 0) {
                    x = spec4[i2 >> 1];
                } else {
                    const float2 lo = spec2[i2];
                    const float2 hi = spec2[i2 + 1];
                    x = make_float4(lo.x, lo.y, hi.x, hi.y);
                }
            }
            fr0 += x.x * cr0[k] - x.y * ci0[k];
            fi0 += x.x * ci0[k] + x.y * cr0[k];
            fr1 += x.z * cr1[k] - x.w * ci1[k];
            fi1 += x.z * ci1[k] + x.w * cr1[k];
        }

        const size_t o2 = (size_t)r * F_DIM + j;
        if ((o2 & 1) == 0) {
            out4[o2 >> 1] = make_float4(fr0, fi0, fr1, fi1);
        } else {
            out2[o2]     = make_float2(fr0, fi0);
            out2[o2 + 1] = make_float2(fr1, fi1);
        }
    }

    // ---------------- Phase 2: copy items (bins 96..480) ----------------
    for (int it = tid; it < CP_ITEMS; it += stride) {
        const int r = it / 193;
        const int k = it - r * 193;
        const size_t rowbase = (size_t)r * F_DIM;   // float2 index; parity = r&1

        if ((r & 1) == 0) {
            if (k < 192) {
                const size_t i4 = ((rowbase + NDF) >> 1) + k;
                out4[i4] = spec4[i4];
            } else {
                out2[rowbase + 480] = spec2[rowbase + 480];
            }
        } else {
            if (k == 0) {
                out2[rowbase + NDF] = spec2[rowbase + NDF];
            } else {
                const size_t i4 = ((rowbase + NDF + 1) >> 1) + (k - 1);
                out4[i4] = spec4[i4];
            }
        }
    }
}

extern "C" void kernel_launch(void* const* d_in, const int* in_sizes, int n_in,
                              void* d_out, int out_size)
{
    const float* spec = (const float*)d_in[0];
    const float* coef = (const float*)d_in[1];
    float* out        = (float*)d_out;

    df_kernel<<<1184, 256>>>(spec, coef, out);   // 8 blocks / SM on 148 SMs
}

// round 4
// speedup vs baseline: 1.3767x; 1.3767x over previous
#include <cuda_runtime.h>

// DfOp: complex order-5 causal FIR on first 96 freq bins, copy the rest.
// spec: (B=8, T=3000, F=481, 2) f32 ; coef: (B=8, T=3000, 96, 10) f32
//
// R4 = R1 (proven-best structure: one block per row, one DF bin per thread)
// with ONLY the copy tail vectorized to float4. DF path byte-identical math.

#define T_DIM 3000
#define F_DIM 481
#define NDF   96
#define NO    5

__global__ __launch_bounds__(256) void df_kernel(
    const float* __restrict__ spec,
    const float* __restrict__ coef,
    float* __restrict__ out)
{
    const int bt = blockIdx.x;          // row = b*T + t
    const int t  = bt % T_DIM;

    const float2* __restrict__ spec2 = reinterpret_cast<const float2*>(spec);
    const float4* __restrict__ spec4 = reinterpret_cast<const float4*>(spec);
    float2* __restrict__ out2 = reinterpret_cast<float2*>(out);
    float4* __restrict__ out4 = reinterpret_cast<float4*>(out);

    const size_t row = (size_t)bt * F_DIM;     // float2 units
    const int tid = threadIdx.x;

    if (tid < NDF) {
        // ---- DF path: one bin per thread (R1 structure, unchanged) ----
        const int f = tid;
        const float* __restrict__ c = coef + ((size_t)bt * NDF + f) * (2 * NO);

        // 5 x LDG.64: coef row is 8B-aligned (byte offset = 40*(bt*96+f))
        const float2* __restrict__ c2 = reinterpret_cast<const float2*>(c);
        const float2 p0 = c2[0], p1 = c2[1], p2 = c2[2], p3 = c2[3], p4 = c2[4];
        const float cr[NO] = {p0.x, p0.y, p1.x, p1.y, p2.x};
        const float ci[NO] = {p2.y, p3.x, p3.y, p4.x, p4.y};

        float fr = 0.f, fi = 0.f;
        #pragma unroll
        for (int k = 0; k < NO; ++k) {
            const int tk = t - (NO - 1) + k;
            float2 x = make_float2(0.f, 0.f);
            if (tk >= 0)
                x = spec2[((size_t)(bt - (NO - 1) + k)) * F_DIM + f];
            fr += x.x * cr[k] - x.y * ci[k];
            fi += x.x * ci[k] + x.y * cr[k];
        }
        out2[row + f] = make_float2(fr, fi);
    } else {
        // ---- Copy path: bins [96,481) = 385 float2 = 192 float4 + 1 float2 ----
        // Row parity decides which end carries the scalar float2 (uniform branch).
        const int ct = tid - NDF;                  // 0..159
        const bool odd = (bt & 1);
        // base float2 index of the aligned float4 run
        const size_t v4base = (row + NDF + (odd ? 1 : 0)) >> 1;

        // float4 item ct
        {
            const size_t i4 = v4base + ct;
            out4[i4] = spec4[i4];
        }
        // float4 items 160..191 handled by threads ct<32
        if (ct < 32) {
            const size_t i4 = v4base + 160 + ct;
            out4[i4] = spec4[i4];
        }
        // leftover scalar float2 (f=480 even rows, f=96 odd rows)
        if (ct == 32) {
            const size_t i2 = row + (odd ? NDF : (F_DIM - 1));
            out2[i2] = spec2[i2];
        }
    }
}

extern "C" void kernel_launch(void* const* d_in, const int* in_sizes, int n_in,
                              void* d_out, int out_size)
{
    const float* spec = (const float*)d_in[0];
    const float* coef = (const float*)d_in[1];
    float* out        = (float*)d_out;

    df_kernel<<<8 * T_DIM, 256>>>(spec, coef, out);
}